// round 15
// baseline (speedup 1.0000x reference)
#include <cuda_runtime.h>
#include <cuda_bf16.h>
#include <cuda_fp16.h>
#include <math.h>
#include <stdint.h>

#define NN 50000
#define EE 800000
#define EMB 64
#define HID 128

// ---------------- scratch (device globals; no allocation allowed) ----------------
__device__ float g_deg[NN];
__device__ float g_dinv[NN];
__device__ int   g_cnt[NN];
__device__ int   g_off[NN + 1];
__device__ int   g_cur[NN];
__device__ int   g_bsum[64];
__device__ int   g_srcs[EE];
__device__ float g_wsrt[EE];

__device__ __align__(16) float  g_z[NN * EMB];     // state (fp32, exact for output+GEMM)
__device__ __align__(16) __half g_z16[NN * EMB];   // fp16 shadow for gathering
__device__ __align__(16) float  g_h[NN * HID];     // activations (fp32 for GEMM)
__device__ __align__(16) __half g_h16[NN * HID];   // fp16 shadow for gathering
__device__ __align__(16) __half g_p1[NN * HID];    // hop buffers (fp16)
__device__ __align__(16) __half g_p2[NN * HID];
__device__ __align__(16) __half g_p3[NN * HID];
__device__ __align__(16) __half g_y0[NN * EMB];    // tag3 GEMM outputs (fp16)
__device__ __align__(16) __half g_y1[NN * EMB];
__device__ __align__(16) __half g_y2[NN * EMB];
__device__ __align__(16) __half g_y3[NN * EMB];
__device__ __align__(16) float g_pp1[NN * 3];
__device__ __align__(16) float g_pp2[NN * 3];
__device__ __align__(16) float g_pp3[NN * 3];
__device__ __align__(16) float g_posacc[NN * HID];

// pre-split, pre-transposed weights: [hop][s=hi/lo][n(128)][k(CINH)] bf16
__device__ __align__(16) __nv_bfloat16 g_wt1[4 * 2 * 128 * 64];
__device__ __align__(16) __nv_bfloat16 g_wt2[4 * 2 * 128 * 128];
__device__ __align__(16) __nv_bfloat16 g_wt3[2 * 2 * 128 * 128];

__device__ __forceinline__ float gelu_exact(float x) {
    return 0.5f * x * (1.0f + erff(x * 0.70710678118654752f));
}

// fast fp32 pair -> packed bf16 hi/lo
__device__ __forceinline__ void split2f(float x, float y, uint32_t& hi, uint32_t& lo) {
    asm("cvt.rn.bf16x2.f32 %0, %1, %2;" : "=r"(hi) : "f"(y), "f"(x));
    float h0 = __uint_as_float(hi << 16);
    float h1 = __uint_as_float(hi & 0xFFFF0000u);
    float r0 = x - h0, r1 = y - h1;
    asm("cvt.rn.bf16x2.f32 %0, %1, %2;" : "=r"(lo) : "f"(r1), "f"(r0));
}

// typed 2ch / 4ch row loads
__device__ __forceinline__ float2 ld2(const float* p) { return *(const float2*)p; }
__device__ __forceinline__ float2 ld2(const __half* p) {
    __half2 h = *(const __half2*)p;
    return __half22float2(h);
}
__device__ __forceinline__ float4 ld4(const float* p) { return *(const float4*)p; }
__device__ __forceinline__ float4 ld4(const __half* p) {
    uint2 u = *(const uint2*)p;
    float2 a = __half22float2(*reinterpret_cast<__half2*>(&u.x));
    float2 b = __half22float2(*reinterpret_cast<__half2*>(&u.y));
    return make_float4(a.x, a.y, b.x, b.y);
}
__device__ __forceinline__ void st2(float* p, float x, float y) {
    *(float2*)p = make_float2(x, y);
}
__device__ __forceinline__ void st2(__half* p, float x, float y) {
    *(__half2*)p = __floats2half2_rn(x, y);
}
__device__ __forceinline__ void st4(float* p, float4 v) { *(float4*)p = v; }
__device__ __forceinline__ void st4(__half* p, float4 v) {
    uint2 u;
    __half2 a = __floats2half2_rn(v.x, v.y);
    __half2 b = __floats2half2_rn(v.z, v.w);
    u.x = *reinterpret_cast<uint32_t*>(&a);
    u.y = *reinterpret_cast<uint32_t*>(&b);
    *(uint2*)p = u;
}

// ---------------- mma.sync helper (bf16, m16n8k16, fp32 acc) ----------------
__device__ __forceinline__ void mma16816(float* d, const uint32_t* a, uint32_t b0, uint32_t b1) {
    asm volatile(
        "mma.sync.aligned.m16n8k16.row.col.f32.bf16.bf16.f32 "
        "{%0,%1,%2,%3}, {%4,%5,%6,%7}, {%8,%9}, {%0,%1,%2,%3};"
        : "+f"(d[0]), "+f"(d[1]), "+f"(d[2]), "+f"(d[3])
        : "r"(a[0]), "r"(a[1]), "r"(a[2]), "r"(a[3]), "r"(b0), "r"(b1));
}

// ---------------- setup kernels ----------------
__global__ void k_zero() {
    int i = blockIdx.x * blockDim.x + threadIdx.x;
    if (i < NN) { g_deg[i] = 0.f; g_cnt[i] = 0; }
}

__global__ void k_hist(const int* __restrict__ col, const float* __restrict__ ea) {
    int e = blockIdx.x * blockDim.x + threadIdx.x;
    if (e < EE) {
        int c = col[e];
        atomicAdd(&g_deg[c], ea[e]);
        atomicAdd(&g_cnt[c], 1);
    }
}

__global__ void k_dinv() {
    int i = blockIdx.x * blockDim.x + threadIdx.x;
    if (i < NN) {
        float d = g_deg[i];
        g_dinv[i] = (d > 0.f) ? rsqrtf(d) : 0.f;
    }
}

__global__ void k_scan1() {
    __shared__ int sh[1024];
    int blk = blockIdx.x, tid = threadIdx.x;
    int i = blk * 1024 + tid;
    int v = (i < NN) ? g_cnt[i] : 0;
    sh[tid] = v;
    __syncthreads();
    for (int ofs = 1; ofs < 1024; ofs <<= 1) {
        int t = (tid >= ofs) ? sh[tid - ofs] : 0;
        __syncthreads();
        sh[tid] += t;
        __syncthreads();
    }
    if (i < NN) g_off[i] = sh[tid] - v;
    if (tid == 1023) g_bsum[blk] = sh[1023];
}

__global__ void k_scan2(int nblk) {
    __shared__ int sh[64];
    int tid = threadIdx.x;
    int v = (tid < nblk) ? g_bsum[tid] : 0;
    sh[tid] = v;
    __syncthreads();
    for (int ofs = 1; ofs < 64; ofs <<= 1) {
        int t = (tid >= ofs) ? sh[tid - ofs] : 0;
        __syncthreads();
        sh[tid] += t;
        __syncthreads();
    }
    g_bsum[tid] = sh[tid] - v;
}

__global__ void k_scan3() {
    int i = blockIdx.x * blockDim.x + threadIdx.x;
    if (i < NN) {
        int o = g_off[i] + g_bsum[i >> 10];
        g_off[i] = o;
        g_cur[i] = o;
    }
    if (i == 0) g_off[NN] = EE;
}

__global__ void k_scatter(const int* __restrict__ row, const int* __restrict__ col,
                          const float* __restrict__ ea) {
    int e = blockIdx.x * blockDim.x + threadIdx.x;
    if (e < EE) {
        int r = row[e], c = col[e];
        int p = atomicAdd(&g_cur[c], 1);
        g_srcs[p] = r;
        g_wsrt[p] = g_dinv[r] * ea[e] * g_dinv[c];
    }
}

// ---------------- weight prep ----------------
__device__ __forceinline__ void split_store(__nv_bfloat16* hi, __nv_bfloat16* lo, float w) {
    __nv_bfloat16 hb = __float2bfloat16(w);
    *hi = hb;
    *lo = __float2bfloat16(w - __bfloat162float(hb));
}

__global__ void k_wprep1(const float* __restrict__ c1w) {
    int idx = blockIdx.x * blockDim.x + threadIdx.x;
    if (idx >= 4 * 128 * 64) return;
    int hop = idx / (128 * 64);
    int r = idx - hop * 128 * 64;
    int n = r >> 6, k = r & 63;
    float w = c1w[hop * 67 * 128 + k * 128 + n];
    size_t b = ((size_t)(hop * 2) * 128 + n) * 64 + k;
    split_store(&g_wt1[b], &g_wt1[b + 128 * 64], w);
}

__global__ void k_wprep2(const float* __restrict__ c2w) {
    int idx = blockIdx.x * blockDim.x + threadIdx.x;
    if (idx >= 4 * 128 * 128) return;
    int hop = idx / (128 * 128);
    int r = idx - hop * 128 * 128;
    int n = r >> 7, k = r & 127;
    float w = c2w[hop * 128 * 128 + k * 128 + n];
    size_t b = ((size_t)(hop * 2) * 128 + n) * 128 + k;
    split_store(&g_wt2[b], &g_wt2[b + 128 * 128], w);
}

__global__ void k_wprep3(const float* __restrict__ c3w) {
    int idx = blockIdx.x * blockDim.x + threadIdx.x;
    if (idx >= 2 * 128 * 128) return;
    int pair = idx / (128 * 128);
    int r = idx - pair * 128 * 128;
    int n = r >> 7, k = r & 127;
    int wk = pair * 2 + (n >> 6);
    int nn = n & 63;
    float w = c3w[wk * 128 * 64 + k * 64 + nn];
    size_t b = ((size_t)(pair * 2) * 128 + n) * 128 + k;
    split_store(&g_wt3[b], &g_wt3[b + 128 * 128], w);
}

// ---------------- pos hops + posacc ----------------
__global__ void k_prop3(float* __restrict__ dst, const float* __restrict__ src) {
    int j = blockIdx.x * blockDim.x + threadIdx.x;
    if (j >= NN) return;
    int beg = g_off[j], end = g_off[j + 1];
    float a0 = 0.f, a1 = 0.f, a2 = 0.f;
    for (int e = beg; e < end; e++) {
        int s = g_srcs[e];
        float w = g_wsrt[e];
        a0 += w * src[s * 3 + 0];
        a1 += w * src[s * 3 + 1];
        a2 += w * src[s * 3 + 2];
    }
    dst[j * 3 + 0] = a0; dst[j * 3 + 1] = a1; dst[j * 3 + 2] = a2;
}

__global__ void k_posacc(const float* __restrict__ pos, const float* __restrict__ c1w) {
    int idx = blockIdx.x * blockDim.x + threadIdx.x;
    if (idx >= NN * HID) return;
    int n = idx >> 7, c = idx & 127;
    const float* pps[4] = {pos, g_pp1, g_pp2, g_pp3};
    float acc = 0.f;
#pragma unroll
    for (int k = 0; k < 4; k++) {
        const float* pp = pps[k] + n * 3;
        const float* wr = c1w + k * 67 * 128 + 64 * 128 + c;
        acc += pp[0] * wr[0] + pp[1] * wr[128] + pp[2] * wr[256];
    }
    g_posacc[idx] = acc;
}

// ---------------- up MLP (writes z fp32 + z16 shadow) ----------------
__global__ __launch_bounds__(256) void k_up(const float* __restrict__ x,
                                            const float* __restrict__ w1, const float* __restrict__ b1,
                                            const float* __restrict__ w2, const float* __restrict__ b2) {
    __shared__ float sw2[64 * 64];
    __shared__ float hid[4][64];
    int tid = threadIdx.x;
#pragma unroll
    for (int i = 0; i < 16; i++) sw2[tid * 16 + i] = w2[tid * 16 + i];
    int local = tid >> 6;
    int c = tid & 63;
    int node = blockIdx.x * 4 + local;
    float h = 0.f;
    if (node < NN) {
        h = b1[c];
#pragma unroll
        for (int i = 0; i < 4; i++) h += x[node * 4 + i] * w1[i * 64 + c];
        h = gelu_exact(h);
    }
    hid[local][c] = h;
    __syncthreads();
    if (node < NN) {
        float o = b2[c];
#pragma unroll
        for (int j = 0; j < 64; j++) o += hid[local][j] * sw2[j * 64 + c];
        g_z[node * 64 + c] = o;
        g_z16[node * 64 + c] = __float2half_rn(o);
    }
}

// ---------------- propagation kernels (CSR, warp/node, round-11 loop, typed) ------
template <typename TS, typename TD>
__global__ __launch_bounds__(256) void k_prop64(TD* __restrict__ dst, const TS* __restrict__ src) {
    int wrp = threadIdx.x >> 5, lane = threadIdx.x & 31;
    int j = blockIdx.x * 8 + wrp;
    if (j >= NN) return;
    int beg = g_off[j], end = g_off[j + 1];
    float2 a0 = {0.f,0.f}, a1 = {0.f,0.f}, a2 = {0.f,0.f}, a3 = {0.f,0.f};
    int e = beg;
    for (; e + 4 <= end; e += 4) {
        int s0 = g_srcs[e], s1 = g_srcs[e+1], s2 = g_srcs[e+2], s3 = g_srcs[e+3];
        float w0 = g_wsrt[e], w1 = g_wsrt[e+1], w2 = g_wsrt[e+2], w3 = g_wsrt[e+3];
        float2 v0 = ld2(src + (size_t)s0 * 64 + lane * 2);
        float2 v1 = ld2(src + (size_t)s1 * 64 + lane * 2);
        float2 v2 = ld2(src + (size_t)s2 * 64 + lane * 2);
        float2 v3 = ld2(src + (size_t)s3 * 64 + lane * 2);
        a0.x = fmaf(w0, v0.x, a0.x); a0.y = fmaf(w0, v0.y, a0.y);
        a1.x = fmaf(w1, v1.x, a1.x); a1.y = fmaf(w1, v1.y, a1.y);
        a2.x = fmaf(w2, v2.x, a2.x); a2.y = fmaf(w2, v2.y, a2.y);
        a3.x = fmaf(w3, v3.x, a3.x); a3.y = fmaf(w3, v3.y, a3.y);
    }
    for (; e < end; e++) {
        int s0 = g_srcs[e];
        float w0 = g_wsrt[e];
        float2 v0 = ld2(src + (size_t)s0 * 64 + lane * 2);
        a0.x = fmaf(w0, v0.x, a0.x); a0.y = fmaf(w0, v0.y, a0.y);
    }
    st2(dst + (size_t)j * 64 + lane * 2,
        (a0.x + a1.x) + (a2.x + a3.x),
        (a0.y + a1.y) + (a2.y + a3.y));
}

template <typename TS, typename TD>
__global__ __launch_bounds__(256) void k_prop128(TD* __restrict__ dst, const TS* __restrict__ src) {
    int wrp = threadIdx.x >> 5, lane = threadIdx.x & 31;
    int j = blockIdx.x * 8 + wrp;
    if (j >= NN) return;
    int beg = g_off[j], end = g_off[j + 1];
    float4 a0 = {0.f,0.f,0.f,0.f}, a1 = {0.f,0.f,0.f,0.f};
    float4 a2 = {0.f,0.f,0.f,0.f}, a3 = {0.f,0.f,0.f,0.f};
    int e = beg;
    for (; e + 4 <= end; e += 4) {
        int s0 = g_srcs[e], s1 = g_srcs[e+1], s2 = g_srcs[e+2], s3 = g_srcs[e+3];
        float w0 = g_wsrt[e], w1 = g_wsrt[e+1], w2 = g_wsrt[e+2], w3 = g_wsrt[e+3];
        float4 v0 = ld4(src + (size_t)s0 * 128 + lane * 4);
        float4 v1 = ld4(src + (size_t)s1 * 128 + lane * 4);
        float4 v2 = ld4(src + (size_t)s2 * 128 + lane * 4);
        float4 v3 = ld4(src + (size_t)s3 * 128 + lane * 4);
        a0.x = fmaf(w0, v0.x, a0.x); a0.y = fmaf(w0, v0.y, a0.y);
        a0.z = fmaf(w0, v0.z, a0.z); a0.w = fmaf(w0, v0.w, a0.w);
        a1.x = fmaf(w1, v1.x, a1.x); a1.y = fmaf(w1, v1.y, a1.y);
        a1.z = fmaf(w1, v1.z, a1.z); a1.w = fmaf(w1, v1.w, a1.w);
        a2.x = fmaf(w2, v2.x, a2.x); a2.y = fmaf(w2, v2.y, a2.y);
        a2.z = fmaf(w2, v2.z, a2.z); a2.w = fmaf(w2, v2.w, a2.w);
        a3.x = fmaf(w3, v3.x, a3.x); a3.y = fmaf(w3, v3.y, a3.y);
        a3.z = fmaf(w3, v3.z, a3.z); a3.w = fmaf(w3, v3.w, a3.w);
    }
    for (; e < end; e++) {
        int s0 = g_srcs[e];
        float w0 = g_wsrt[e];
        float4 v0 = ld4(src + (size_t)s0 * 128 + lane * 4);
        a0.x = fmaf(w0, v0.x, a0.x); a0.y = fmaf(w0, v0.y, a0.y);
        a0.z = fmaf(w0, v0.z, a0.z); a0.w = fmaf(w0, v0.w, a0.w);
    }
    float4 r;
    r.x = (a0.x + a1.x) + (a2.x + a3.x);
    r.y = (a0.y + a1.y) + (a2.y + a3.y);
    r.z = (a0.z + a1.z) + (a2.z + a3.z);
    r.w = (a0.w + a1.w) + (a2.w + a3.w);
    st4(dst + (size_t)j * 128 + lane * 4, r);
}

// tag3: dst(fp16) = P src(fp16) + add(fp16)
__global__ __launch_bounds__(256) void k_propadd64(__half* __restrict__ dst, const __half* __restrict__ src,
                                                   const __half* __restrict__ add) {
    int wrp = threadIdx.x >> 5, lane = threadIdx.x & 31;
    int j = blockIdx.x * 8 + wrp;
    if (j >= NN) return;
    int beg = g_off[j], end = g_off[j + 1];
    float2 a0 = {0.f,0.f}, a1 = {0.f,0.f}, a2 = {0.f,0.f}, a3 = {0.f,0.f};
    int e = beg;
    for (; e + 4 <= end; e += 4) {
        int s0 = g_srcs[e], s1 = g_srcs[e+1], s2 = g_srcs[e+2], s3 = g_srcs[e+3];
        float w0 = g_wsrt[e], w1 = g_wsrt[e+1], w2 = g_wsrt[e+2], w3 = g_wsrt[e+3];
        float2 v0 = ld2(src + (size_t)s0 * 64 + lane * 2);
        float2 v1 = ld2(src + (size_t)s1 * 64 + lane * 2);
        float2 v2 = ld2(src + (size_t)s2 * 64 + lane * 2);
        float2 v3 = ld2(src + (size_t)s3 * 64 + lane * 2);
        a0.x = fmaf(w0, v0.x, a0.x); a0.y = fmaf(w0, v0.y, a0.y);
        a1.x = fmaf(w1, v1.x, a1.x); a1.y = fmaf(w1, v1.y, a1.y);
        a2.x = fmaf(w2, v2.x, a2.x); a2.y = fmaf(w2, v2.y, a2.y);
        a3.x = fmaf(w3, v3.x, a3.x); a3.y = fmaf(w3, v3.y, a3.y);
    }
    for (; e < end; e++) {
        int s0 = g_srcs[e];
        float w0 = g_wsrt[e];
        float2 v0 = ld2(src + (size_t)s0 * 64 + lane * 2);
        a0.x = fmaf(w0, v0.x, a0.x); a0.y = fmaf(w0, v0.y, a0.y);
    }
    float2 ad = ld2(add + (size_t)j * 64 + lane * 2);
    st2(dst + (size_t)j * 64 + lane * 2,
        (a0.x + a1.x) + (a2.x + a3.x) + ad.x,
        (a0.y + a1.y) + (a2.y + a3.y) + ad.y);
}

// tag3 final: z(fp32 + fp16 shadow) = log_softmax(P src + add + bias)
__global__ __launch_bounds__(256) void k_proplogsm(const __half* __restrict__ src,
                                                   const __half* __restrict__ add,
                                                   const float* __restrict__ bias) {
    int wrp = threadIdx.x >> 5, lane = threadIdx.x & 31;
    int j = blockIdx.x * 8 + wrp;
    if (j >= NN) return;
    int beg = g_off[j], end = g_off[j + 1];
    float2 a0 = {0.f,0.f}, a1 = {0.f,0.f}, a2 = {0.f,0.f}, a3 = {0.f,0.f};
    int e = beg;
    for (; e + 4 <= end; e += 4) {
        int s0 = g_srcs[e], s1 = g_srcs[e+1], s2 = g_srcs[e+2], s3 = g_srcs[e+3];
        float w0 = g_wsrt[e], w1 = g_wsrt[e+1], w2 = g_wsrt[e+2], w3 = g_wsrt[e+3];
        float2 v0 = ld2(src + (size_t)s0 * 64 + lane * 2);
        float2 v1 = ld2(src + (size_t)s1 * 64 + lane * 2);
        float2 v2 = ld2(src + (size_t)s2 * 64 + lane * 2);
        float2 v3 = ld2(src + (size_t)s3 * 64 + lane * 2);
        a0.x = fmaf(w0, v0.x, a0.x); a0.y = fmaf(w0, v0.y, a0.y);
        a1.x = fmaf(w1, v1.x, a1.x); a1.y = fmaf(w1, v1.y, a1.y);
        a2.x = fmaf(w2, v2.x, a2.x); a2.y = fmaf(w2, v2.y, a2.y);
        a3.x = fmaf(w3, v3.x, a3.x); a3.y = fmaf(w3, v3.y, a3.y);
    }
    for (; e < end; e++) {
        int s0 = g_srcs[e];
        float w0 = g_wsrt[e];
        float2 v0 = ld2(src + (size_t)s0 * 64 + lane * 2);
        a0.x = fmaf(w0, v0.x, a0.x); a0.y = fmaf(w0, v0.y, a0.y);
    }
    float2 ad = ld2(add + (size_t)j * 64 + lane * 2);
    float v0 = (a0.x + a1.x) + (a2.x + a3.x) + ad.x + bias[2 * lane];
    float v1 = (a0.y + a1.y) + (a2.y + a3.y) + ad.y + bias[2 * lane + 1];
    float m = fmaxf(v0, v1);
#pragma unroll
    for (int o = 16; o; o >>= 1) m = fmaxf(m, __shfl_xor_sync(0xffffffffu, m, o));
    float s = expf(v0 - m) + expf(v1 - m);
#pragma unroll
    for (int o = 16; o; o >>= 1) s += __shfl_xor_sync(0xffffffffu, s, o);
    float l = m + logf(s);
    float r0 = v0 - l, r1 = v1 - l;
    g_z[j * 64 + 2 * lane]     = r0;
    g_z[j * 64 + 2 * lane + 1] = r1;
    st2(g_z16 + (size_t)j * 64 + 2 * lane, r0, r1);
}

// ---------------- tensor GEMM via mma.sync (M=64 CTA tiles, 2M x 4N warps) --------
// A0 fp32 (z or h), A1..A3 fp16 (hop buffers); optional fp16 shadow output
template <int CINH, int NHOPS>
__global__ __launch_bounds__(256)
void k_mma(const float* __restrict__ A0, const __half* __restrict__ A1,
           const __half* __restrict__ A2, const __half* __restrict__ A3,
           const __nv_bfloat16* __restrict__ Wt,
           const float* __restrict__ addend, const float* __restrict__ bias,
           float* __restrict__ out0, __half* __restrict__ out16) {
    constexpr int ASTR = CINH + 8;
    extern __shared__ __align__(16) char sm[];
    __nv_bfloat16* sAhi = (__nv_bfloat16*)sm;
    __nv_bfloat16* sAlo = sAhi + 64 * ASTR;
    __nv_bfloat16* sWhi = sAlo + 64 * ASTR;
    __nv_bfloat16* sWlo = sWhi + 128 * ASTR;

    int tid = threadIdx.x, wid = tid >> 5, lane = tid & 31;
    int wm = wid & 1, wn = wid >> 1;
    int grp = lane >> 2, tig = lane & 3;

    float acc[2][4][4];
#pragma unroll
    for (int i = 0; i < 2; i++)
#pragma unroll
        for (int j = 0; j < 4; j++)
#pragma unroll
            for (int q = 0; q < 4; q++) acc[i][j][q] = 0.f;

    const __half* Ahs[4] = {nullptr, A1, A2, A3};
    int row0 = blockIdx.x * 64;
    constexpr int KQ4 = CINH / 4;
    constexpr int KQ8 = CINH / 8;

    for (int h = 0; h < NHOPS; h++) {
        if (h) __syncthreads();
        for (int u = tid; u < 64 * KQ4; u += 256) {
            int r = u / KQ4;
            int k4 = (u - r * KQ4) * 4;
            int grow = row0 + r;
            float4 f;
            if (grow < NN) {
                if (h == 0) f = ld4(A0 + (size_t)grow * CINH + k4);
                else        f = ld4(Ahs[h] + (size_t)grow * CINH + k4);
            } else { f.x = f.y = f.z = f.w = 0.f; }
            uint32_t hp0, lp0, hp1, lp1;
            split2f(f.x, f.y, hp0, lp0);
            split2f(f.z, f.w, hp1, lp1);
            *(uint2*)(sAhi + r * ASTR + k4) = make_uint2(hp0, hp1);
            *(uint2*)(sAlo + r * ASTR + k4) = make_uint2(lp0, lp1);
        }
        for (int u = tid; u < 2 * 128 * KQ8; u += 256) {
            int s = u / (128 * KQ8);
            int rem = u - s * 128 * KQ8;
            int n = rem / KQ8;
            int k8 = (rem - n * KQ8) * 8;
            uint4 vv = *(const uint4*)(Wt + ((size_t)((h * 2 + s) * 128 + n)) * CINH + k8);
            *(uint4*)((s ? sWlo : sWhi) + n * ASTR + k8) = vv;
        }
        __syncthreads();

#pragma unroll
        for (int pass = 0; pass < 3; pass++) {
            const __nv_bfloat16* Ab = (pass == 2) ? sAlo : sAhi;
            const __nv_bfloat16* Wb = (pass == 1) ? sWlo : sWhi;
#pragma unroll
            for (int k8 = 0; k8 < CINH / 16; k8++) {
                uint32_t a[2][4];
                const __nv_bfloat16* ab = Ab + (wm * 32 + grp) * ASTR + k8 * 16 + 2 * tig;
#pragma unroll
                for (int ms = 0; ms < 2; ms++) {
                    const __nv_bfloat16* p = ab + ms * 16 * ASTR;
                    a[ms][0] = *(const uint32_t*)p;
                    a[ms][1] = *(const uint32_t*)(p + 8 * ASTR);
                    a[ms][2] = *(const uint32_t*)(p + 8);
                    a[ms][3] = *(const uint32_t*)(p + 8 * ASTR + 8);
                }
                const __nv_bfloat16* bb = Wb + (wn * 32 + grp) * ASTR + k8 * 16 + 2 * tig;
#pragma unroll
                for (int n8 = 0; n8 < 4; n8++) {
                    uint32_t b0 = *(const uint32_t*)(bb + n8 * 8 * ASTR);
                    uint32_t b1 = *(const uint32_t*)(bb + n8 * 8 * ASTR + 8);
                    mma16816(acc[0][n8], a[0], b0, b1);
                    mma16816(acc[1][n8], a[1], b0, b1);
                }
            }
        }
    }

#pragma unroll
    for (int ms = 0; ms < 2; ms++) {
        int r0 = row0 + wm * 32 + ms * 16 + grp;
        int r1 = r0 + 8;
#pragma unroll
        for (int n8 = 0; n8 < 4; n8++) {
            int cb = wn * 32 + n8 * 8 + 2 * tig;
            float* d = acc[ms][n8];
            float b0v = __ldg(bias + cb), b1v = __ldg(bias + cb + 1);
            if (r0 < NN) {
                float v0 = d[0] + b0v, v1 = d[1] + b1v;
                if (addend) {
                    float2 ad = *(const float2*)(addend + (size_t)r0 * 128 + cb);
                    v0 += ad.x; v1 += ad.y;
                }
                v0 = fmaxf(v0, 0.f); v1 = fmaxf(v1, 0.f);
                st2(out0 + (size_t)r0 * 128 + cb, v0, v1);
                if (out16) st2(out16 + (size_t)r0 * 128 + cb, v0, v1);
            }
            if (r1 < NN) {
                float v0 = d[2] + b0v, v1 = d[3] + b1v;
                if (addend) {
                    float2 ad = *(const float2*)(addend + (size_t)r1 * 128 + cb);
                    v0 += ad.x; v1 += ad.y;
                }
                v0 = fmaxf(v0, 0.f); v1 = fmaxf(v1, 0.f);
                st2(out0 + (size_t)r1 * 128 + cb, v0, v1);
                if (out16) st2(out16 + (size_t)r1 * 128 + cb, v0, v1);
            }
        }
    }
}

// ---------------- tag3 GEMM: M=64 tiles, one A fill, two W pair sets -> y0..y3 (fp16)
__global__ __launch_bounds__(256)
void k_mma3(const float* __restrict__ A, const __nv_bfloat16* __restrict__ Wt,
            __half* __restrict__ y0, __half* __restrict__ y1,
            __half* __restrict__ y2, __half* __restrict__ y3) {
    constexpr int CINH = 128;
    constexpr int ASTR = CINH + 8;
    extern __shared__ __align__(16) char sm[];
    __nv_bfloat16* sAhi = (__nv_bfloat16*)sm;
    __nv_bfloat16* sAlo = sAhi + 64 * ASTR;
    __nv_bfloat16* sWhi = sAlo + 64 * ASTR;
    __nv_bfloat16* sWlo = sWhi + 128 * ASTR;

    int tid = threadIdx.x, wid = tid >> 5, lane = tid & 31;
    int wm = wid & 1, wn = wid >> 1;
    int grp = lane >> 2, tig = lane & 3;
    int row0 = blockIdx.x * 64;
    constexpr int KQ4 = CINH / 4;
    constexpr int KQ8 = CINH / 8;

    for (int u = tid; u < 64 * KQ4; u += 256) {
        int r = u / KQ4;
        int k4 = (u - r * KQ4) * 4;
        int grow = row0 + r;
        float4 f;
        if (grow < NN) f = *(const float4*)(A + (size_t)grow * CINH + k4);
        else { f.x = f.y = f.z = f.w = 0.f; }
        uint32_t hp0, lp0, hp1, lp1;
        split2f(f.x, f.y, hp0, lp0);
        split2f(f.z, f.w, hp1, lp1);
        *(uint2*)(sAhi + r * ASTR + k4) = make_uint2(hp0, hp1);
        *(uint2*)(sAlo + r * ASTR + k4) = make_uint2(lp0, lp1);
    }

    for (int set = 0; set < 2; set++) {
        const __nv_bfloat16* Wp = Wt + (size_t)set * 2 * 128 * CINH;
        for (int u = tid; u < 2 * 128 * KQ8; u += 256) {
            int s = u / (128 * KQ8);
            int rem = u - s * 128 * KQ8;
            int n = rem / KQ8;
            int k8 = (rem - n * KQ8) * 8;
            uint4 vv = *(const uint4*)(Wp + ((size_t)(s * 128 + n)) * CINH + k8);
            *(uint4*)((s ? sWlo : sWhi) + n * ASTR + k8) = vv;
        }
        __syncthreads();

        float acc[2][4][4];
#pragma unroll
        for (int i = 0; i < 2; i++)
#pragma unroll
            for (int j = 0; j < 4; j++)
#pragma unroll
                for (int q = 0; q < 4; q++) acc[i][j][q] = 0.f;

#pragma unroll
        for (int pass = 0; pass < 3; pass++) {
            const __nv_bfloat16* Ab = (pass == 2) ? sAlo : sAhi;
            const __nv_bfloat16* Wb = (pass == 1) ? sWlo : sWhi;
#pragma unroll
            for (int k8 = 0; k8 < CINH / 16; k8++) {
                uint32_t a[2][4];
                const __nv_bfloat16* ab = Ab + (wm * 32 + grp) * ASTR + k8 * 16 + 2 * tig;
#pragma unroll
                for (int ms = 0; ms < 2; ms++) {
                    const __nv_bfloat16* p = ab + ms * 16 * ASTR;
                    a[ms][0] = *(const uint32_t*)p;
                    a[ms][1] = *(const uint32_t*)(p + 8 * ASTR);
                    a[ms][2] = *(const uint32_t*)(p + 8);
                    a[ms][3] = *(const uint32_t*)(p + 8 * ASTR + 8);
                }
                const __nv_bfloat16* bb = Wb + (wn * 32 + grp) * ASTR + k8 * 16 + 2 * tig;
#pragma unroll
                for (int n8 = 0; n8 < 4; n8++) {
                    uint32_t b0 = *(const uint32_t*)(bb + n8 * 8 * ASTR);
                    uint32_t b1 = *(const uint32_t*)(bb + n8 * 8 * ASTR + 8);
                    mma16816(acc[0][n8], a[0], b0, b1);
                    mma16816(acc[1][n8], a[1], b0, b1);
                }
            }
        }

        __half* oA = set ? y2 : y0;
        __half* oB = set ? y3 : y1;
        __half* op = (wn < 2) ? oA : oB;
        int cbase = (wn & 1) * 32;
#pragma unroll
        for (int ms = 0; ms < 2; ms++) {
            int r0 = row0 + wm * 32 + ms * 16 + grp;
            int r1 = r0 + 8;
#pragma unroll
            for (int n8 = 0; n8 < 4; n8++) {
                int cc = cbase + n8 * 8 + 2 * tig;
                float* d = acc[ms][n8];
                if (r0 < NN) st2(op + (size_t)r0 * 64 + cc, d[0], d[1]);
                if (r1 < NN) st2(op + (size_t)r1 * 64 + cc, d[2], d[3]);
            }
        }
        __syncthreads();
    }
}

// ---------------- down MLP + output write ----------------
__global__ __launch_bounds__(256) void k_down(float* __restrict__ out,
                                              const float* __restrict__ w1, const float* __restrict__ b1,
                                              const float* __restrict__ w2, const float* __restrict__ b2) {
    int wrp = threadIdx.x >> 5, lane = threadIdx.x & 31;
    int j = blockIdx.x * 8 + wrp;
    if (j >= NN) return;
    float z0 = g_z[j * 64 + lane];
    float z1 = g_z[j * 64 + 32 + lane];
    out[NN + j * 64 + lane] = z0;
    out[NN + j * 64 + 32 + lane] = z1;
    float d = z0 * w1[lane] + z1 * w1[32 + lane];
#pragma unroll
    for (int o = 16; o; o >>= 1) d += __shfl_xor_sync(0xffffffffu, d, o);
    if (lane == 0) out[j] = gelu_exact(d + b1[0]) * w2[0] + b2[0];
}

// ---------------- host orchestration ----------------
extern "C" void kernel_launch(void* const* d_in, const int* in_sizes, int n_in,
                              void* d_out, int out_size) {
    const float* x      = (const float*)d_in[0];
    const float* pos    = (const float*)d_in[1];
    const float* ea     = (const float*)d_in[2];
    const float* up_w1  = (const float*)d_in[3];
    const float* up_b1  = (const float*)d_in[4];
    const float* up_w2  = (const float*)d_in[5];
    const float* up_b2  = (const float*)d_in[6];
    const float* c1_w   = (const float*)d_in[7];
    const float* c1_b   = (const float*)d_in[8];
    const float* c2_w   = (const float*)d_in[9];
    const float* c2_b   = (const float*)d_in[10];
    const float* c3_w   = (const float*)d_in[11];
    const float* c3_b   = (const float*)d_in[12];
    const float* dw1    = (const float*)d_in[13];
    const float* db1    = (const float*)d_in[14];
    const float* dw2    = (const float*)d_in[15];
    const float* db2    = (const float*)d_in[16];
    const int*   ei     = (const int*)d_in[17];
    const int* row = ei;
    const int* col = ei + EE;

    float *z, *h, *pp1, *pp2, *pp3, *posacc;
    __half *z16, *h16, *p1, *p2, *p3, *y0, *y1, *y2, *y3;
    __nv_bfloat16 *wt1, *wt2, *wt3;
    cudaGetSymbolAddress((void**)&z,      g_z);
    cudaGetSymbolAddress((void**)&z16,    g_z16);
    cudaGetSymbolAddress((void**)&h,      g_h);
    cudaGetSymbolAddress((void**)&h16,    g_h16);
    cudaGetSymbolAddress((void**)&p1,     g_p1);
    cudaGetSymbolAddress((void**)&p2,     g_p2);
    cudaGetSymbolAddress((void**)&p3,     g_p3);
    cudaGetSymbolAddress((void**)&y0,     g_y0);
    cudaGetSymbolAddress((void**)&y1,     g_y1);
    cudaGetSymbolAddress((void**)&y2,     g_y2);
    cudaGetSymbolAddress((void**)&y3,     g_y3);
    cudaGetSymbolAddress((void**)&pp1,    g_pp1);
    cudaGetSymbolAddress((void**)&pp2,    g_pp2);
    cudaGetSymbolAddress((void**)&pp3,    g_pp3);
    cudaGetSymbolAddress((void**)&posacc, g_posacc);
    cudaGetSymbolAddress((void**)&wt1,    g_wt1);
    cudaGetSymbolAddress((void**)&wt2,    g_wt2);
    cudaGetSymbolAddress((void**)&wt3,    g_wt3);

    const int SM64  = (2 * 64 + 2 * 128) * (64 + 8) * 2;    // 55296
    const int SM128 = (2 * 64 + 2 * 128) * (128 + 8) * 2;   // 104448
    cudaFuncSetAttribute((const void*)k_mma<64, 4>,  cudaFuncAttributeMaxDynamicSharedMemorySize, SM64);
    cudaFuncSetAttribute((const void*)k_mma<128, 4>, cudaFuncAttributeMaxDynamicSharedMemorySize, SM128);
    cudaFuncSetAttribute((const void*)k_mma3,        cudaFuncAttributeMaxDynamicSharedMemorySize, SM128);

    const int GN = (NN + 255) / 256;
    const int GE = (EE + 255) / 256;
    const int GW = (NN + 7) / 8;
    const int GT = (NN + 63) / 64;
    const int GP = (NN * HID + 255) / 256;
    const int NB = (NN + 1023) / 1024;

    // --- graph setup ---
    k_zero<<<GN, 256>>>();
    k_hist<<<GE, 256>>>(col, ea);
    k_dinv<<<GN, 256>>>();
    k_scan1<<<NB, 1024>>>();
    k_scan2<<<1, 64>>>(NB);
    k_scan3<<<GN, 256>>>();
    k_scatter<<<GE, 256>>>(row, col, ea);

    // --- weight prep ---
    k_wprep1<<<(4 * 128 * 64 + 255) / 256, 256>>>(c1_w);
    k_wprep2<<<(4 * 128 * 128 + 255) / 256, 256>>>(c2_w);
    k_wprep3<<<(2 * 128 * 128 + 255) / 256, 256>>>(c3_w);

    // --- iteration-invariant pos hops + posacc ---
    k_prop3<<<GN, 256>>>(pp1, pos);
    k_prop3<<<GN, 256>>>(pp2, pp1);
    k_prop3<<<GN, 256>>>(pp3, pp2);
    k_posacc<<<GP, 256>>>(pos, c1_w);

    // --- up MLP -> z0 (+ z16 shadow) ---
    k_up<<<(NN + 3) / 4, 256>>>(x, up_w1, up_b1, up_w2, up_b2);

    // --- 21 gnn applications ---
    for (int it = 0; it < 21; it++) {
        // tag1: hops on z16 (all-fp16 gathers), tensor GEMM (+posacc, relu) -> h + h16
        k_prop64<__half, __half><<<GW, 256>>>(p1, z16);
        k_prop64<__half, __half><<<GW, 256>>>(p2, p1);
        k_prop64<__half, __half><<<GW, 256>>>(p3, p2);
        k_mma<64, 4><<<GT, 256, SM64>>>(z, p1, p2, p3, wt1, posacc, c1_b, h, h16);

        // tag2: hops on h16 (all-fp16 gathers), tensor GEMM (relu) -> h (fp32 only)
        k_prop128<__half, __half><<<GW, 256>>>(p1, h16);
        k_prop128<__half, __half><<<GW, 256>>>(p2, p1);
        k_prop128<__half, __half><<<GW, 256>>>(p3, p2);
        k_mma<128, 4><<<GT, 256, SM128>>>(h, p1, p2, p3, wt2, nullptr, c2_b, h, nullptr);

        // tag3: merged GEMM (fp16 y's), then fp16 prop chain -> z (fp32 + z16)
        k_mma3<<<GT, 256, SM128>>>(h, wt3, y0, y1, y2, y3);
        k_propadd64<<<GW, 256>>>(p1, y3, y2);
        k_propadd64<<<GW, 256>>>(p2, p1, y1);
        k_proplogsm<<<GW, 256>>>(p2, y0, c3_b);
    }

    // --- down MLP + write (out, z_star) ---
    k_down<<<GW, 256>>>((float*)d_out, dw1, db1, dw2, db2);

    (void)in_sizes; (void)n_in; (void)out_size;
}

// round 16
// speedup vs baseline: 1.0218x; 1.0218x over previous
#include <cuda_runtime.h>
#include <cuda_bf16.h>
#include <cuda_fp16.h>
#include <math.h>
#include <stdint.h>

#define NN 50000
#define EE 800000
#define EMB 64
#define HID 128

// ---------------- scratch (device globals; no allocation allowed) ----------------
__device__ float g_deg[NN];
__device__ float g_dinv[NN];
__device__ int   g_cnt[NN];
__device__ int   g_off[NN + 1];
__device__ int   g_cur[NN];
__device__ int   g_bsum[64];
__device__ int   g_srcs[EE];
__device__ float g_wsrt[EE];

__device__ __align__(16) __half g_z[NN * EMB];     // state (fp16)
__device__ __align__(16) __half g_h[NN * HID];     // activations (fp16)
__device__ __align__(16) __half g_p1[NN * HID];    // hop buffers (fp16)
__device__ __align__(16) __half g_p2[NN * HID];
__device__ __align__(16) __half g_p3[NN * HID];
__device__ __align__(16) __half g_y0[NN * EMB];    // tag3 GEMM outputs (fp16)
__device__ __align__(16) __half g_y1[NN * EMB];
__device__ __align__(16) __half g_y2[NN * EMB];
__device__ __align__(16) __half g_y3[NN * EMB];
__device__ __align__(16) float g_pp1[NN * 3];
__device__ __align__(16) float g_pp2[NN * 3];
__device__ __align__(16) float g_pp3[NN * 3];
__device__ __align__(16) float g_posacc[NN * HID];

// pre-split, pre-transposed weights: [hop][s=hi/lo][n(128)][k(CINH)] bf16
__device__ __align__(16) __nv_bfloat16 g_wt1[4 * 2 * 128 * 64];
__device__ __align__(16) __nv_bfloat16 g_wt2[4 * 2 * 128 * 128];
__device__ __align__(16) __nv_bfloat16 g_wt3[2 * 2 * 128 * 128];

__device__ __forceinline__ float gelu_exact(float x) {
    return 0.5f * x * (1.0f + erff(x * 0.70710678118654752f));
}

// fast fp32 pair -> packed bf16 hi/lo
__device__ __forceinline__ void split2f(float x, float y, uint32_t& hi, uint32_t& lo) {
    asm("cvt.rn.bf16x2.f32 %0, %1, %2;" : "=r"(hi) : "f"(y), "f"(x));
    float h0 = __uint_as_float(hi << 16);
    float h1 = __uint_as_float(hi & 0xFFFF0000u);
    float r0 = x - h0, r1 = y - h1;
    asm("cvt.rn.bf16x2.f32 %0, %1, %2;" : "=r"(lo) : "f"(r1), "f"(r0));
}

// typed 2ch / 4ch row loads
__device__ __forceinline__ float2 ld2(const float* p) { return *(const float2*)p; }
__device__ __forceinline__ float2 ld2(const __half* p) {
    __half2 h = *(const __half2*)p;
    return __half22float2(h);
}
__device__ __forceinline__ float4 ld4(const float* p) { return *(const float4*)p; }
__device__ __forceinline__ float4 ld4(const __half* p) {
    uint2 u = *(const uint2*)p;
    float2 a = __half22float2(*reinterpret_cast<__half2*>(&u.x));
    float2 b = __half22float2(*reinterpret_cast<__half2*>(&u.y));
    return make_float4(a.x, a.y, b.x, b.y);
}
__device__ __forceinline__ void st2(float* p, float x, float y) {
    *(float2*)p = make_float2(x, y);
}
__device__ __forceinline__ void st2(__half* p, float x, float y) {
    *(__half2*)p = __floats2half2_rn(x, y);
}
__device__ __forceinline__ void st4(__half* p, float4 v) {
    uint2 u;
    __half2 a = __floats2half2_rn(v.x, v.y);
    __half2 b = __floats2half2_rn(v.z, v.w);
    u.x = *reinterpret_cast<uint32_t*>(&a);
    u.y = *reinterpret_cast<uint32_t*>(&b);
    *(uint2*)p = u;
}

// ---------------- mma.sync helper (bf16, m16n8k16, fp32 acc) ----------------
__device__ __forceinline__ void mma16816(float* d, const uint32_t* a, uint32_t b0, uint32_t b1) {
    asm volatile(
        "mma.sync.aligned.m16n8k16.row.col.f32.bf16.bf16.f32 "
        "{%0,%1,%2,%3}, {%4,%5,%6,%7}, {%8,%9}, {%0,%1,%2,%3};"
        : "+f"(d[0]), "+f"(d[1]), "+f"(d[2]), "+f"(d[3])
        : "r"(a[0]), "r"(a[1]), "r"(a[2]), "r"(a[3]), "r"(b0), "r"(b1));
}

// ---------------- setup kernels ----------------
__global__ void k_zero() {
    int i = blockIdx.x * blockDim.x + threadIdx.x;
    if (i < NN) { g_deg[i] = 0.f; g_cnt[i] = 0; }
}

__global__ void k_hist(const int* __restrict__ col, const float* __restrict__ ea) {
    int e = blockIdx.x * blockDim.x + threadIdx.x;
    if (e < EE) {
        int c = col[e];
        atomicAdd(&g_deg[c], ea[e]);
        atomicAdd(&g_cnt[c], 1);
    }
}

__global__ void k_dinv() {
    int i = blockIdx.x * blockDim.x + threadIdx.x;
    if (i < NN) {
        float d = g_deg[i];
        g_dinv[i] = (d > 0.f) ? rsqrtf(d) : 0.f;
    }
}

__global__ void k_scan1() {
    __shared__ int sh[1024];
    int blk = blockIdx.x, tid = threadIdx.x;
    int i = blk * 1024 + tid;
    int v = (i < NN) ? g_cnt[i] : 0;
    sh[tid] = v;
    __syncthreads();
    for (int ofs = 1; ofs < 1024; ofs <<= 1) {
        int t = (tid >= ofs) ? sh[tid - ofs] : 0;
        __syncthreads();
        sh[tid] += t;
        __syncthreads();
    }
    if (i < NN) g_off[i] = sh[tid] - v;
    if (tid == 1023) g_bsum[blk] = sh[1023];
}

__global__ void k_scan2(int nblk) {
    __shared__ int sh[64];
    int tid = threadIdx.x;
    int v = (tid < nblk) ? g_bsum[tid] : 0;
    sh[tid] = v;
    __syncthreads();
    for (int ofs = 1; ofs < 64; ofs <<= 1) {
        int t = (tid >= ofs) ? sh[tid - ofs] : 0;
        __syncthreads();
        sh[tid] += t;
        __syncthreads();
    }
    g_bsum[tid] = sh[tid] - v;
}

__global__ void k_scan3() {
    int i = blockIdx.x * blockDim.x + threadIdx.x;
    if (i < NN) {
        int o = g_off[i] + g_bsum[i >> 10];
        g_off[i] = o;
        g_cur[i] = o;
    }
    if (i == 0) g_off[NN] = EE;
}

__global__ void k_scatter(const int* __restrict__ row, const int* __restrict__ col,
                          const float* __restrict__ ea) {
    int e = blockIdx.x * blockDim.x + threadIdx.x;
    if (e < EE) {
        int r = row[e], c = col[e];
        int p = atomicAdd(&g_cur[c], 1);
        g_srcs[p] = r;
        g_wsrt[p] = g_dinv[r] * ea[e] * g_dinv[c];
    }
}

// ---------------- weight prep ----------------
__device__ __forceinline__ void split_store(__nv_bfloat16* hi, __nv_bfloat16* lo, float w) {
    __nv_bfloat16 hb = __float2bfloat16(w);
    *hi = hb;
    *lo = __float2bfloat16(w - __bfloat162float(hb));
}

__global__ void k_wprep1(const float* __restrict__ c1w) {
    int idx = blockIdx.x * blockDim.x + threadIdx.x;
    if (idx >= 4 * 128 * 64) return;
    int hop = idx / (128 * 64);
    int r = idx - hop * 128 * 64;
    int n = r >> 6, k = r & 63;
    float w = c1w[hop * 67 * 128 + k * 128 + n];
    size_t b = ((size_t)(hop * 2) * 128 + n) * 64 + k;
    split_store(&g_wt1[b], &g_wt1[b + 128 * 64], w);
}

__global__ void k_wprep2(const float* __restrict__ c2w) {
    int idx = blockIdx.x * blockDim.x + threadIdx.x;
    if (idx >= 4 * 128 * 128) return;
    int hop = idx / (128 * 128);
    int r = idx - hop * 128 * 128;
    int n = r >> 7, k = r & 127;
    float w = c2w[hop * 128 * 128 + k * 128 + n];
    size_t b = ((size_t)(hop * 2) * 128 + n) * 128 + k;
    split_store(&g_wt2[b], &g_wt2[b + 128 * 128], w);
}

__global__ void k_wprep3(const float* __restrict__ c3w) {
    int idx = blockIdx.x * blockDim.x + threadIdx.x;
    if (idx >= 2 * 128 * 128) return;
    int pair = idx / (128 * 128);
    int r = idx - pair * 128 * 128;
    int n = r >> 7, k = r & 127;
    int wk = pair * 2 + (n >> 6);
    int nn = n & 63;
    float w = c3w[wk * 128 * 64 + k * 64 + nn];
    size_t b = ((size_t)(pair * 2) * 128 + n) * 128 + k;
    split_store(&g_wt3[b], &g_wt3[b + 128 * 128], w);
}

// ---------------- pos hops + posacc ----------------
__global__ void k_prop3(float* __restrict__ dst, const float* __restrict__ src) {
    int j = blockIdx.x * blockDim.x + threadIdx.x;
    if (j >= NN) return;
    int beg = g_off[j], end = g_off[j + 1];
    float a0 = 0.f, a1 = 0.f, a2 = 0.f;
    for (int e = beg; e < end; e++) {
        int s = g_srcs[e];
        float w = g_wsrt[e];
        a0 += w * src[s * 3 + 0];
        a1 += w * src[s * 3 + 1];
        a2 += w * src[s * 3 + 2];
    }
    dst[j * 3 + 0] = a0; dst[j * 3 + 1] = a1; dst[j * 3 + 2] = a2;
}

__global__ void k_posacc(const float* __restrict__ pos, const float* __restrict__ c1w) {
    int idx = blockIdx.x * blockDim.x + threadIdx.x;
    if (idx >= NN * HID) return;
    int n = idx >> 7, c = idx & 127;
    const float* pps[4] = {pos, g_pp1, g_pp2, g_pp3};
    float acc = 0.f;
#pragma unroll
    for (int k = 0; k < 4; k++) {
        const float* pp = pps[k] + n * 3;
        const float* wr = c1w + k * 67 * 128 + 64 * 128 + c;
        acc += pp[0] * wr[0] + pp[1] * wr[128] + pp[2] * wr[256];
    }
    g_posacc[idx] = acc;
}

// ---------------- up MLP (writes z fp16) ----------------
__global__ __launch_bounds__(256) void k_up(const float* __restrict__ x,
                                            const float* __restrict__ w1, const float* __restrict__ b1,
                                            const float* __restrict__ w2, const float* __restrict__ b2) {
    __shared__ float sw2[64 * 64];
    __shared__ float hid[4][64];
    int tid = threadIdx.x;
#pragma unroll
    for (int i = 0; i < 16; i++) sw2[tid * 16 + i] = w2[tid * 16 + i];
    int local = tid >> 6;
    int c = tid & 63;
    int node = blockIdx.x * 4 + local;
    float h = 0.f;
    if (node < NN) {
        h = b1[c];
#pragma unroll
        for (int i = 0; i < 4; i++) h += x[node * 4 + i] * w1[i * 64 + c];
        h = gelu_exact(h);
    }
    hid[local][c] = h;
    __syncthreads();
    if (node < NN) {
        float o = b2[c];
#pragma unroll
        for (int j = 0; j < 64; j++) o += hid[local][j] * sw2[j * 64 + c];
        g_z[node * 64 + c] = __float2half_rn(o);
    }
}

// ---------------- propagation kernels (CSR, warp/node, fp16) ----------
__global__ __launch_bounds__(256) void k_prop64(__half* __restrict__ dst, const __half* __restrict__ src) {
    int wrp = threadIdx.x >> 5, lane = threadIdx.x & 31;
    int j = blockIdx.x * 8 + wrp;
    if (j >= NN) return;
    int beg = g_off[j], end = g_off[j + 1];
    float2 a0 = {0.f,0.f}, a1 = {0.f,0.f}, a2 = {0.f,0.f}, a3 = {0.f,0.f};
    int e = beg;
    for (; e + 4 <= end; e += 4) {
        int s0 = g_srcs[e], s1 = g_srcs[e+1], s2 = g_srcs[e+2], s3 = g_srcs[e+3];
        float w0 = g_wsrt[e], w1 = g_wsrt[e+1], w2 = g_wsrt[e+2], w3 = g_wsrt[e+3];
        float2 v0 = ld2(src + (size_t)s0 * 64 + lane * 2);
        float2 v1 = ld2(src + (size_t)s1 * 64 + lane * 2);
        float2 v2 = ld2(src + (size_t)s2 * 64 + lane * 2);
        float2 v3 = ld2(src + (size_t)s3 * 64 + lane * 2);
        a0.x = fmaf(w0, v0.x, a0.x); a0.y = fmaf(w0, v0.y, a0.y);
        a1.x = fmaf(w1, v1.x, a1.x); a1.y = fmaf(w1, v1.y, a1.y);
        a2.x = fmaf(w2, v2.x, a2.x); a2.y = fmaf(w2, v2.y, a2.y);
        a3.x = fmaf(w3, v3.x, a3.x); a3.y = fmaf(w3, v3.y, a3.y);
    }
    for (; e < end; e++) {
        int s0 = g_srcs[e];
        float w0 = g_wsrt[e];
        float2 v0 = ld2(src + (size_t)s0 * 64 + lane * 2);
        a0.x = fmaf(w0, v0.x, a0.x); a0.y = fmaf(w0, v0.y, a0.y);
    }
    st2(dst + (size_t)j * 64 + lane * 2,
        (a0.x + a1.x) + (a2.x + a3.x),
        (a0.y + a1.y) + (a2.y + a3.y));
}

__global__ __launch_bounds__(256) void k_prop128(__half* __restrict__ dst, const __half* __restrict__ src) {
    int wrp = threadIdx.x >> 5, lane = threadIdx.x & 31;
    int j = blockIdx.x * 8 + wrp;
    if (j >= NN) return;
    int beg = g_off[j], end = g_off[j + 1];
    float4 a0 = {0.f,0.f,0.f,0.f}, a1 = {0.f,0.f,0.f,0.f};
    float4 a2 = {0.f,0.f,0.f,0.f}, a3 = {0.f,0.f,0.f,0.f};
    int e = beg;
    for (; e + 4 <= end; e += 4) {
        int s0 = g_srcs[e], s1 = g_srcs[e+1], s2 = g_srcs[e+2], s3 = g_srcs[e+3];
        float w0 = g_wsrt[e], w1 = g_wsrt[e+1], w2 = g_wsrt[e+2], w3 = g_wsrt[e+3];
        float4 v0 = ld4(src + (size_t)s0 * 128 + lane * 4);
        float4 v1 = ld4(src + (size_t)s1 * 128 + lane * 4);
        float4 v2 = ld4(src + (size_t)s2 * 128 + lane * 4);
        float4 v3 = ld4(src + (size_t)s3 * 128 + lane * 4);
        a0.x = fmaf(w0, v0.x, a0.x); a0.y = fmaf(w0, v0.y, a0.y);
        a0.z = fmaf(w0, v0.z, a0.z); a0.w = fmaf(w0, v0.w, a0.w);
        a1.x = fmaf(w1, v1.x, a1.x); a1.y = fmaf(w1, v1.y, a1.y);
        a1.z = fmaf(w1, v1.z, a1.z); a1.w = fmaf(w1, v1.w, a1.w);
        a2.x = fmaf(w2, v2.x, a2.x); a2.y = fmaf(w2, v2.y, a2.y);
        a2.z = fmaf(w2, v2.z, a2.z); a2.w = fmaf(w2, v2.w, a2.w);
        a3.x = fmaf(w3, v3.x, a3.x); a3.y = fmaf(w3, v3.y, a3.y);
        a3.z = fmaf(w3, v3.z, a3.z); a3.w = fmaf(w3, v3.w, a3.w);
    }
    for (; e < end; e++) {
        int s0 = g_srcs[e];
        float w0 = g_wsrt[e];
        float4 v0 = ld4(src + (size_t)s0 * 128 + lane * 4);
        a0.x = fmaf(w0, v0.x, a0.x); a0.y = fmaf(w0, v0.y, a0.y);
        a0.z = fmaf(w0, v0.z, a0.z); a0.w = fmaf(w0, v0.w, a0.w);
    }
    float4 r;
    r.x = (a0.x + a1.x) + (a2.x + a3.x);
    r.y = (a0.y + a1.y) + (a2.y + a3.y);
    r.z = (a0.z + a1.z) + (a2.z + a3.z);
    r.w = (a0.w + a1.w) + (a2.w + a3.w);
    st4(dst + (size_t)j * 128 + lane * 4, r);
}

// tag3: dst(fp16) = P src(fp16) + add(fp16)
__global__ __launch_bounds__(256) void k_propadd64(__half* __restrict__ dst, const __half* __restrict__ src,
                                                   const __half* __restrict__ add) {
    int wrp = threadIdx.x >> 5, lane = threadIdx.x & 31;
    int j = blockIdx.x * 8 + wrp;
    if (j >= NN) return;
    int beg = g_off[j], end = g_off[j + 1];
    float2 a0 = {0.f,0.f}, a1 = {0.f,0.f}, a2 = {0.f,0.f}, a3 = {0.f,0.f};
    int e = beg;
    for (; e + 4 <= end; e += 4) {
        int s0 = g_srcs[e], s1 = g_srcs[e+1], s2 = g_srcs[e+2], s3 = g_srcs[e+3];
        float w0 = g_wsrt[e], w1 = g_wsrt[e+1], w2 = g_wsrt[e+2], w3 = g_wsrt[e+3];
        float2 v0 = ld2(src + (size_t)s0 * 64 + lane * 2);
        float2 v1 = ld2(src + (size_t)s1 * 64 + lane * 2);
        float2 v2 = ld2(src + (size_t)s2 * 64 + lane * 2);
        float2 v3 = ld2(src + (size_t)s3 * 64 + lane * 2);
        a0.x = fmaf(w0, v0.x, a0.x); a0.y = fmaf(w0, v0.y, a0.y);
        a1.x = fmaf(w1, v1.x, a1.x); a1.y = fmaf(w1, v1.y, a1.y);
        a2.x = fmaf(w2, v2.x, a2.x); a2.y = fmaf(w2, v2.y, a2.y);
        a3.x = fmaf(w3, v3.x, a3.x); a3.y = fmaf(w3, v3.y, a3.y);
    }
    for (; e < end; e++) {
        int s0 = g_srcs[e];
        float w0 = g_wsrt[e];
        float2 v0 = ld2(src + (size_t)s0 * 64 + lane * 2);
        a0.x = fmaf(w0, v0.x, a0.x); a0.y = fmaf(w0, v0.y, a0.y);
    }
    float2 ad = ld2(add + (size_t)j * 64 + lane * 2);
    st2(dst + (size_t)j * 64 + lane * 2,
        (a0.x + a1.x) + (a2.x + a3.x) + ad.x,
        (a0.y + a1.y) + (a2.y + a3.y) + ad.y);
}

// tag3 final: z(fp16) = log_softmax(P src + add + bias)
__global__ __launch_bounds__(256) void k_proplogsm(const __half* __restrict__ src,
                                                   const __half* __restrict__ add,
                                                   const float* __restrict__ bias) {
    int wrp = threadIdx.x >> 5, lane = threadIdx.x & 31;
    int j = blockIdx.x * 8 + wrp;
    if (j >= NN) return;
    int beg = g_off[j], end = g_off[j + 1];
    float2 a0 = {0.f,0.f}, a1 = {0.f,0.f}, a2 = {0.f,0.f}, a3 = {0.f,0.f};
    int e = beg;
    for (; e + 4 <= end; e += 4) {
        int s0 = g_srcs[e], s1 = g_srcs[e+1], s2 = g_srcs[e+2], s3 = g_srcs[e+3];
        float w0 = g_wsrt[e], w1 = g_wsrt[e+1], w2 = g_wsrt[e+2], w3 = g_wsrt[e+3];
        float2 v0 = ld2(src + (size_t)s0 * 64 + lane * 2);
        float2 v1 = ld2(src + (size_t)s1 * 64 + lane * 2);
        float2 v2 = ld2(src + (size_t)s2 * 64 + lane * 2);
        float2 v3 = ld2(src + (size_t)s3 * 64 + lane * 2);
        a0.x = fmaf(w0, v0.x, a0.x); a0.y = fmaf(w0, v0.y, a0.y);
        a1.x = fmaf(w1, v1.x, a1.x); a1.y = fmaf(w1, v1.y, a1.y);
        a2.x = fmaf(w2, v2.x, a2.x); a2.y = fmaf(w2, v2.y, a2.y);
        a3.x = fmaf(w3, v3.x, a3.x); a3.y = fmaf(w3, v3.y, a3.y);
    }
    for (; e < end; e++) {
        int s0 = g_srcs[e];
        float w0 = g_wsrt[e];
        float2 v0 = ld2(src + (size_t)s0 * 64 + lane * 2);
        a0.x = fmaf(w0, v0.x, a0.x); a0.y = fmaf(w0, v0.y, a0.y);
    }
    float2 ad = ld2(add + (size_t)j * 64 + lane * 2);
    float v0 = (a0.x + a1.x) + (a2.x + a3.x) + ad.x + bias[2 * lane];
    float v1 = (a0.y + a1.y) + (a2.y + a3.y) + ad.y + bias[2 * lane + 1];
    float m = fmaxf(v0, v1);
#pragma unroll
    for (int o = 16; o; o >>= 1) m = fmaxf(m, __shfl_xor_sync(0xffffffffu, m, o));
    float s = expf(v0 - m) + expf(v1 - m);
#pragma unroll
    for (int o = 16; o; o >>= 1) s += __shfl_xor_sync(0xffffffffu, s, o);
    float l = m + logf(s);
    st2(g_z + (size_t)j * 64 + 2 * lane, v0 - l, v1 - l);
}

// ---------------- tensor GEMM via mma.sync (M=64 CTA tiles, 2M x 4N warps) --------
// all A sources fp16; out fp16
template <int CINH, int NHOPS>
__global__ __launch_bounds__(256)
void k_mma(const __half* __restrict__ A0, const __half* __restrict__ A1,
           const __half* __restrict__ A2, const __half* __restrict__ A3,
           const __nv_bfloat16* __restrict__ Wt,
           const float* __restrict__ addend, const float* __restrict__ bias,
           __half* __restrict__ out0) {
    constexpr int ASTR = CINH + 8;
    extern __shared__ __align__(16) char sm[];
    __nv_bfloat16* sAhi = (__nv_bfloat16*)sm;
    __nv_bfloat16* sAlo = sAhi + 64 * ASTR;
    __nv_bfloat16* sWhi = sAlo + 64 * ASTR;
    __nv_bfloat16* sWlo = sWhi + 128 * ASTR;

    int tid = threadIdx.x, wid = tid >> 5, lane = tid & 31;
    int wm = wid & 1, wn = wid >> 1;
    int grp = lane >> 2, tig = lane & 3;

    float acc[2][4][4];
#pragma unroll
    for (int i = 0; i < 2; i++)
#pragma unroll
        for (int j = 0; j < 4; j++)
#pragma unroll
            for (int q = 0; q < 4; q++) acc[i][j][q] = 0.f;

    const __half* Ahs[4] = {A0, A1, A2, A3};
    int row0 = blockIdx.x * 64;
    constexpr int KQ4 = CINH / 4;
    constexpr int KQ8 = CINH / 8;

    for (int h = 0; h < NHOPS; h++) {
        if (h) __syncthreads();
        const __half* Ah = Ahs[h];
        for (int u = tid; u < 64 * KQ4; u += 256) {
            int r = u / KQ4;
            int k4 = (u - r * KQ4) * 4;
            int grow = row0 + r;
            float4 f;
            if (grow < NN) f = ld4(Ah + (size_t)grow * CINH + k4);
            else { f.x = f.y = f.z = f.w = 0.f; }
            uint32_t hp0, lp0, hp1, lp1;
            split2f(f.x, f.y, hp0, lp0);
            split2f(f.z, f.w, hp1, lp1);
            *(uint2*)(sAhi + r * ASTR + k4) = make_uint2(hp0, hp1);
            *(uint2*)(sAlo + r * ASTR + k4) = make_uint2(lp0, lp1);
        }
        for (int u = tid; u < 2 * 128 * KQ8; u += 256) {
            int s = u / (128 * KQ8);
            int rem = u - s * 128 * KQ8;
            int n = rem / KQ8;
            int k8 = (rem - n * KQ8) * 8;
            uint4 vv = *(const uint4*)(Wt + ((size_t)((h * 2 + s) * 128 + n)) * CINH + k8);
            *(uint4*)((s ? sWlo : sWhi) + n * ASTR + k8) = vv;
        }
        __syncthreads();

#pragma unroll
        for (int pass = 0; pass < 3; pass++) {
            const __nv_bfloat16* Ab = (pass == 2) ? sAlo : sAhi;
            const __nv_bfloat16* Wb = (pass == 1) ? sWlo : sWhi;
#pragma unroll
            for (int k8 = 0; k8 < CINH / 16; k8++) {
                uint32_t a[2][4];
                const __nv_bfloat16* ab = Ab + (wm * 32 + grp) * ASTR + k8 * 16 + 2 * tig;
#pragma unroll
                for (int ms = 0; ms < 2; ms++) {
                    const __nv_bfloat16* p = ab + ms * 16 * ASTR;
                    a[ms][0] = *(const uint32_t*)p;
                    a[ms][1] = *(const uint32_t*)(p + 8 * ASTR);
                    a[ms][2] = *(const uint32_t*)(p + 8);
                    a[ms][3] = *(const uint32_t*)(p + 8 * ASTR + 8);
                }
                const __nv_bfloat16* bb = Wb + (wn * 32 + grp) * ASTR + k8 * 16 + 2 * tig;
#pragma unroll
                for (int n8 = 0; n8 < 4; n8++) {
                    uint32_t b0 = *(const uint32_t*)(bb + n8 * 8 * ASTR);
                    uint32_t b1 = *(const uint32_t*)(bb + n8 * 8 * ASTR + 8);
                    mma16816(acc[0][n8], a[0], b0, b1);
                    mma16816(acc[1][n8], a[1], b0, b1);
                }
            }
        }
    }

#pragma unroll
    for (int ms = 0; ms < 2; ms++) {
        int r0 = row0 + wm * 32 + ms * 16 + grp;
        int r1 = r0 + 8;
#pragma unroll
        for (int n8 = 0; n8 < 4; n8++) {
            int cb = wn * 32 + n8 * 8 + 2 * tig;
            float* d = acc[ms][n8];
            float b0v = __ldg(bias + cb), b1v = __ldg(bias + cb + 1);
            if (r0 < NN) {
                float v0 = d[0] + b0v, v1 = d[1] + b1v;
                if (addend) {
                    float2 ad = *(const float2*)(addend + (size_t)r0 * 128 + cb);
                    v0 += ad.x; v1 += ad.y;
                }
                st2(out0 + (size_t)r0 * 128 + cb, fmaxf(v0, 0.f), fmaxf(v1, 0.f));
            }
            if (r1 < NN) {
                float v0 = d[2] + b0v, v1 = d[3] + b1v;
                if (addend) {
                    float2 ad = *(const float2*)(addend + (size_t)r1 * 128 + cb);
                    v0 += ad.x; v1 += ad.y;
                }
                st2(out0 + (size_t)r1 * 128 + cb, fmaxf(v0, 0.f), fmaxf(v1, 0.f));
            }
        }
    }
}

// ---------------- tag3 GEMM: M=64 tiles, one A fill, two W pair sets -> y0..y3 (fp16)
__global__ __launch_bounds__(256)
void k_mma3(const __half* __restrict__ A, const __nv_bfloat16* __restrict__ Wt,
            __half* __restrict__ y0, __half* __restrict__ y1,
            __half* __restrict__ y2, __half* __restrict__ y3) {
    constexpr int CINH = 128;
    constexpr int ASTR = CINH + 8;
    extern __shared__ __align__(16) char sm[];
    __nv_bfloat16* sAhi = (__nv_bfloat16*)sm;
    __nv_bfloat16* sAlo = sAhi + 64 * ASTR;
    __nv_bfloat16* sWhi = sAlo + 64 * ASTR;
    __nv_bfloat16* sWlo = sWhi + 128 * ASTR;

    int tid = threadIdx.x, wid = tid >> 5, lane = tid & 31;
    int wm = wid & 1, wn = wid >> 1;
    int grp = lane >> 2, tig = lane & 3;
    int row0 = blockIdx.x * 64;
    constexpr int KQ4 = CINH / 4;
    constexpr int KQ8 = CINH / 8;

    for (int u = tid; u < 64 * KQ4; u += 256) {
        int r = u / KQ4;
        int k4 = (u - r * KQ4) * 4;
        int grow = row0 + r;
        float4 f;
        if (grow < NN) f = ld4(A + (size_t)grow * CINH + k4);
        else { f.x = f.y = f.z = f.w = 0.f; }
        uint32_t hp0, lp0, hp1, lp1;
        split2f(f.x, f.y, hp0, lp0);
        split2f(f.z, f.w, hp1, lp1);
        *(uint2*)(sAhi + r * ASTR + k4) = make_uint2(hp0, hp1);
        *(uint2*)(sAlo + r * ASTR + k4) = make_uint2(lp0, lp1);
    }

    for (int set = 0; set < 2; set++) {
        const __nv_bfloat16* Wp = Wt + (size_t)set * 2 * 128 * CINH;
        for (int u = tid; u < 2 * 128 * KQ8; u += 256) {
            int s = u / (128 * KQ8);
            int rem = u - s * 128 * KQ8;
            int n = rem / KQ8;
            int k8 = (rem - n * KQ8) * 8;
            uint4 vv = *(const uint4*)(Wp + ((size_t)(s * 128 + n)) * CINH + k8);
            *(uint4*)((s ? sWlo : sWhi) + n * ASTR + k8) = vv;
        }
        __syncthreads();

        float acc[2][4][4];
#pragma unroll
        for (int i = 0; i < 2; i++)
#pragma unroll
            for (int j = 0; j < 4; j++)
#pragma unroll
                for (int q = 0; q < 4; q++) acc[i][j][q] = 0.f;

#pragma unroll
        for (int pass = 0; pass < 3; pass++) {
            const __nv_bfloat16* Ab = (pass == 2) ? sAlo : sAhi;
            const __nv_bfloat16* Wb = (pass == 1) ? sWlo : sWhi;
#pragma unroll
            for (int k8 = 0; k8 < CINH / 16; k8++) {
                uint32_t a[2][4];
                const __nv_bfloat16* ab = Ab + (wm * 32 + grp) * ASTR + k8 * 16 + 2 * tig;
#pragma unroll
                for (int ms = 0; ms < 2; ms++) {
                    const __nv_bfloat16* p = ab + ms * 16 * ASTR;
                    a[ms][0] = *(const uint32_t*)p;
                    a[ms][1] = *(const uint32_t*)(p + 8 * ASTR);
                    a[ms][2] = *(const uint32_t*)(p + 8);
                    a[ms][3] = *(const uint32_t*)(p + 8 * ASTR + 8);
                }
                const __nv_bfloat16* bb = Wb + (wn * 32 + grp) * ASTR + k8 * 16 + 2 * tig;
#pragma unroll
                for (int n8 = 0; n8 < 4; n8++) {
                    uint32_t b0 = *(const uint32_t*)(bb + n8 * 8 * ASTR);
                    uint32_t b1 = *(const uint32_t*)(bb + n8 * 8 * ASTR + 8);
                    mma16816(acc[0][n8], a[0], b0, b1);
                    mma16816(acc[1][n8], a[1], b0, b1);
                }
            }
        }

        __half* oA = set ? y2 : y0;
        __half* oB = set ? y3 : y1;
        __half* op = (wn < 2) ? oA : oB;
        int cbase = (wn & 1) * 32;
#pragma unroll
        for (int ms = 0; ms < 2; ms++) {
            int r0 = row0 + wm * 32 + ms * 16 + grp;
            int r1 = r0 + 8;
#pragma unroll
            for (int n8 = 0; n8 < 4; n8++) {
                int cc = cbase + n8 * 8 + 2 * tig;
                float* d = acc[ms][n8];
                if (r0 < NN) st2(op + (size_t)r0 * 64 + cc, d[0], d[1]);
                if (r1 < NN) st2(op + (size_t)r1 * 64 + cc, d[2], d[3]);
            }
        }
        __syncthreads();
    }
}

// ---------------- down MLP + output write ----------------
__global__ __launch_bounds__(256) void k_down(float* __restrict__ out,
                                              const float* __restrict__ w1, const float* __restrict__ b1,
                                              const float* __restrict__ w2, const float* __restrict__ b2) {
    int wrp = threadIdx.x >> 5, lane = threadIdx.x & 31;
    int j = blockIdx.x * 8 + wrp;
    if (j >= NN) return;
    float z0 = __half2float(g_z[j * 64 + lane]);
    float z1 = __half2float(g_z[j * 64 + 32 + lane]);
    out[NN + j * 64 + lane] = z0;
    out[NN + j * 64 + 32 + lane] = z1;
    float d = z0 * w1[lane] + z1 * w1[32 + lane];
#pragma unroll
    for (int o = 16; o; o >>= 1) d += __shfl_xor_sync(0xffffffffu, d, o);
    if (lane == 0) out[j] = gelu_exact(d + b1[0]) * w2[0] + b2[0];
}

// ---------------- host orchestration ----------------
extern "C" void kernel_launch(void* const* d_in, const int* in_sizes, int n_in,
                              void* d_out, int out_size) {
    const float* x      = (const float*)d_in[0];
    const float* pos    = (const float*)d_in[1];
    const float* ea     = (const float*)d_in[2];
    const float* up_w1  = (const float*)d_in[3];
    const float* up_b1  = (const float*)d_in[4];
    const float* up_w2  = (const float*)d_in[5];
    const float* up_b2  = (const float*)d_in[6];
    const float* c1_w   = (const float*)d_in[7];
    const float* c1_b   = (const float*)d_in[8];
    const float* c2_w   = (const float*)d_in[9];
    const float* c2_b   = (const float*)d_in[10];
    const float* c3_w   = (const float*)d_in[11];
    const float* c3_b   = (const float*)d_in[12];
    const float* dw1    = (const float*)d_in[13];
    const float* db1    = (const float*)d_in[14];
    const float* dw2    = (const float*)d_in[15];
    const float* db2    = (const float*)d_in[16];
    const int*   ei     = (const int*)d_in[17];
    const int* row = ei;
    const int* col = ei + EE;

    float *pp1, *pp2, *pp3, *posacc;
    __half *z, *h, *p1, *p2, *p3, *y0, *y1, *y2, *y3;
    __nv_bfloat16 *wt1, *wt2, *wt3;
    cudaGetSymbolAddress((void**)&z,      g_z);
    cudaGetSymbolAddress((void**)&h,      g_h);
    cudaGetSymbolAddress((void**)&p1,     g_p1);
    cudaGetSymbolAddress((void**)&p2,     g_p2);
    cudaGetSymbolAddress((void**)&p3,     g_p3);
    cudaGetSymbolAddress((void**)&y0,     g_y0);
    cudaGetSymbolAddress((void**)&y1,     g_y1);
    cudaGetSymbolAddress((void**)&y2,     g_y2);
    cudaGetSymbolAddress((void**)&y3,     g_y3);
    cudaGetSymbolAddress((void**)&pp1,    g_pp1);
    cudaGetSymbolAddress((void**)&pp2,    g_pp2);
    cudaGetSymbolAddress((void**)&pp3,    g_pp3);
    cudaGetSymbolAddress((void**)&posacc, g_posacc);
    cudaGetSymbolAddress((void**)&wt1,    g_wt1);
    cudaGetSymbolAddress((void**)&wt2,    g_wt2);
    cudaGetSymbolAddress((void**)&wt3,    g_wt3);

    const int SM64  = (2 * 64 + 2 * 128) * (64 + 8) * 2;    // 55296
    const int SM128 = (2 * 64 + 2 * 128) * (128 + 8) * 2;   // 104448
    cudaFuncSetAttribute((const void*)k_mma<64, 4>,  cudaFuncAttributeMaxDynamicSharedMemorySize, SM64);
    cudaFuncSetAttribute((const void*)k_mma<128, 4>, cudaFuncAttributeMaxDynamicSharedMemorySize, SM128);
    cudaFuncSetAttribute((const void*)k_mma3,        cudaFuncAttributeMaxDynamicSharedMemorySize, SM128);

    const int GN = (NN + 255) / 256;
    const int GE = (EE + 255) / 256;
    const int GW = (NN + 7) / 8;
    const int GT = (NN + 63) / 64;
    const int GP = (NN * HID + 255) / 256;
    const int NB = (NN + 1023) / 1024;

    // --- graph setup ---
    k_zero<<<GN, 256>>>();
    k_hist<<<GE, 256>>>(col, ea);
    k_dinv<<<GN, 256>>>();
    k_scan1<<<NB, 1024>>>();
    k_scan2<<<1, 64>>>(NB);
    k_scan3<<<GN, 256>>>();
    k_scatter<<<GE, 256>>>(row, col, ea);

    // --- weight prep ---
    k_wprep1<<<(4 * 128 * 64 + 255) / 256, 256>>>(c1_w);
    k_wprep2<<<(4 * 128 * 128 + 255) / 256, 256>>>(c2_w);
    k_wprep3<<<(2 * 128 * 128 + 255) / 256, 256>>>(c3_w);

    // --- iteration-invariant pos hops + posacc ---
    k_prop3<<<GN, 256>>>(pp1, pos);
    k_prop3<<<GN, 256>>>(pp2, pp1);
    k_prop3<<<GN, 256>>>(pp3, pp2);
    k_posacc<<<GP, 256>>>(pos, c1_w);

    // --- up MLP -> z0 (fp16) ---
    k_up<<<(NN + 3) / 4, 256>>>(x, up_w1, up_b1, up_w2, up_b2);

    // --- 21 gnn applications ---
    for (int it = 0; it < 21; it++) {
        // tag1: hops on z (fp16), tensor GEMM (+posacc, relu) -> h (fp16)
        k_prop64<<<GW, 256>>>(p1, z);
        k_prop64<<<GW, 256>>>(p2, p1);
        k_prop64<<<GW, 256>>>(p3, p2);
        k_mma<64, 4><<<GT, 256, SM64>>>(z, p1, p2, p3, wt1, posacc, c1_b, h);

        // tag2: hops on h (fp16), tensor GEMM (relu) -> h (fp16)
        k_prop128<<<GW, 256>>>(p1, h);
        k_prop128<<<GW, 256>>>(p2, p1);
        k_prop128<<<GW, 256>>>(p3, p2);
        k_mma<128, 4><<<GT, 256, SM128>>>(h, p1, p2, p3, wt2, nullptr, c2_b, h);

        // tag3: merged GEMM (fp16 y's), then fp16 prop chain -> z (fp16)
        k_mma3<<<GT, 256, SM128>>>(h, wt3, y0, y1, y2, y3);
        k_propadd64<<<GW, 256>>>(p1, y3, y2);
        k_propadd64<<<GW, 256>>>(p2, p1, y1);
        k_proplogsm<<<GW, 256>>>(p2, y0, c3_b);
    }

    // --- down MLP + write (out, z_star) ---
    k_down<<<GW, 256>>>((float*)d_out, dw1, db1, dw2, db2);

    (void)in_sizes; (void)n_in; (void)out_size;
}